// round 4
// baseline (speedup 1.0000x reference)
#include <cuda_runtime.h>
#include <cuda_bf16.h>
#include <math.h>
#include <stdint.h>

// Problem constants
#define BB    64
#define NN    2048
#define DIN   2
#define DOUT  64
#define DD    10
#define CIN   66          // DIN + DOUT
#define KJ    132         // CHEB_K * CIN
#define KJP   144         // padded to 9 k16 steps
#define GOUT  128         // gate output (2*DOUT)
#define UOUT  64          // update output
#define NCOLS (BB*CIN)    // 4224

// ================= PTX helpers (baseline sm_80+ ISA only) =================
__device__ __forceinline__ uint32_t smem_to_u32(const void* smem_ptr) {
    uint32_t addr;
    asm("{ .reg .u64 tmp; cvta.to.shared.u64 tmp, %1; cvt.u32.u64 %0, tmp; }"
        : "=r"(addr) : "l"(smem_ptr));
    return addr;
}
__device__ __forceinline__ void cpasync16(uint32_t dst, const void* src) {
    asm volatile("cp.async.cg.shared.global [%0], [%1], 16;" :: "r"(dst), "l"(src) : "memory");
}
#define CPASYNC_COMMIT() asm volatile("cp.async.commit_group;" ::: "memory")
#define CPASYNC_WAIT(n)  asm volatile("cp.async.wait_group %0;" :: "n"(n) : "memory")

#define LDMX4(r, addr) \
    asm volatile("ldmatrix.sync.aligned.m8n8.x4.shared.b16 {%0,%1,%2,%3}, [%4];" \
        : "=r"((r)[0]), "=r"((r)[1]), "=r"((r)[2]), "=r"((r)[3]) : "r"(addr))

#define MMA_BF16(d, a, b0, b1) \
    asm volatile("mma.sync.aligned.m16n8k16.row.col.f32.bf16.bf16.f32 " \
        "{%0,%1,%2,%3}, {%4,%5,%6,%7}, {%8,%9}, {%0,%1,%2,%3};" \
        : "+f"((d)[0]), "+f"((d)[1]), "+f"((d)[2]), "+f"((d)[3]) \
        : "r"((a)[0]), "r"((a)[1]), "r"((a)[2]), "r"((a)[3]), "r"(b0), "r"(b1))

// -------- scratch (device globals; no allocation allowed) --------
__device__ __align__(128) __nv_bfloat16 g_Shi [NN*NN];        // bf16 hi of supports [m][k]
__device__ __align__(128) __nv_bfloat16 g_Slo [NN*NN];        // bf16 lo
__device__ __align__(128) float g_xin [NN*BB*CIN];            // concat(x,state)  [n][b][c]
__device__ __align__(128) float g_xg1 [NN*BB*CIN];            // S @ xin          [n][b][c]
__device__ __align__(128) float g_cand[NN*BB*CIN];            // concat(x,z*state)[n][b][c]
__device__ __align__(128) float g_cg1 [NN*BB*CIN];            // S @ cand         [n][b][c]
__device__ __align__(128) __nv_bfloat16 g_xt_hi[NCOLS*NN];    // xin^T bf16 hi [col][k]
__device__ __align__(128) __nv_bfloat16 g_xt_lo[NCOLS*NN];
__device__ __align__(128) __nv_bfloat16 g_ct_hi[NCOLS*NN];    // cand^T bf16 hi
__device__ __align__(128) __nv_bfloat16 g_ct_lo[NCOLS*NN];
__device__ __align__(128) float g_r   [NN*BB*DOUT];
__device__ __align__(128) float g_Wg  [NN*KJ*GOUT];
__device__ __align__(128) float g_Wu  [NN*KJ*UOUT];
__device__ __align__(128) float g_bg  [NN*GOUT];
__device__ __align__(128) float g_bu  [NN*UOUT];

// ---------------------------------------------------------------
// K1: supports = softmax(relu(E E^T)) -> bf16 hi/lo split
// ---------------------------------------------------------------
__global__ __launch_bounds__(256) void supports_kernel(const float* __restrict__ E) {
    const int n   = blockIdx.x;
    const int tid = threadIdx.x;
    __shared__ float en[DD];
    __shared__ float red[256];

    if (tid < DD) en[tid] = E[n*DD + tid];
    __syncthreads();

    float vals[8];
    float vmax = -1e30f;
    #pragma unroll
    for (int i = 0; i < 8; i++) {
        int m = i*256 + tid;
        float dot = 0.f;
        #pragma unroll
        for (int d = 0; d < DD; d++) dot += en[d] * E[m*DD + d];
        float v = dot > 0.f ? dot : 0.f;
        vals[i] = v;
        vmax = fmaxf(vmax, v);
    }
    red[tid] = vmax; __syncthreads();
    for (int s = 128; s > 0; s >>= 1) {
        if (tid < s) red[tid] = fmaxf(red[tid], red[tid + s]);
        __syncthreads();
    }
    vmax = red[0]; __syncthreads();

    float lsum = 0.f;
    #pragma unroll
    for (int i = 0; i < 8; i++) { vals[i] = expf(vals[i] - vmax); lsum += vals[i]; }
    red[tid] = lsum; __syncthreads();
    for (int s = 128; s > 0; s >>= 1) {
        if (tid < s) red[tid] += red[tid + s];
        __syncthreads();
    }
    const float inv = 1.f / red[0];

    #pragma unroll
    for (int i = 0; i < 8; i++) {
        float v = vals[i] * inv;
        __nv_bfloat16 h = __float2bfloat16(v);
        __nv_bfloat16 l = __float2bfloat16(v - __bfloat162float(h));
        size_t off = (size_t)n*NN + i*256 + tid;
        g_Shi[off] = h;
        g_Slo[off] = l;
    }
}

// ---------------------------------------------------------------
// K2: xin[n][b][c] = (c<2) ? x[b][n][c] : state[b][n][c-2]
// ---------------------------------------------------------------
__global__ __launch_bounds__(256) void concat_kernel(const float* __restrict__ x,
                                                     const float* __restrict__ state) {
    int idx = blockIdx.x * 256 + threadIdx.x;
    if (idx >= NN*BB*CIN) return;
    int c  = idx % CIN;
    int nb = idx / CIN;
    int b  = nb % BB;
    int n  = nb / BB;
    float v = (c < DIN) ? x[((size_t)b*NN + n)*DIN + c]
                        : state[((size_t)b*NN + n)*DOUT + (c - DIN)];
    g_xin[idx] = v;
}

// ---------------------------------------------------------------
// K2b: transpose+convert: src fp32 [2048][4224] -> hi/lo bf16 [4224][2048]
// ---------------------------------------------------------------
__global__ __launch_bounds__(256) void transconv_kernel(int which) {
    const float* __restrict__ src = which ? g_cand : g_xin;
    __nv_bfloat16* __restrict__ dhi = which ? g_ct_hi : g_xt_hi;
    __nv_bfloat16* __restrict__ dlo = which ? g_ct_lo : g_xt_lo;

    __shared__ float t[64][129];
    const int tid = threadIdx.x;
    const int c0 = blockIdx.x * 64;
    const int n0 = blockIdx.y * 128;

    #pragma unroll
    for (int it = 0; it < 8; it++) {
        int lin = tid + it*256;
        int r = lin >> 4, q = lin & 15;
        float4 v = *(const float4*)&src[(size_t)(n0 + r)*NCOLS + c0 + q*4];
        t[q*4+0][r] = v.x; t[q*4+1][r] = v.y; t[q*4+2][r] = v.z; t[q*4+3][r] = v.w;
    }
    __syncthreads();

    const int j = tid >> 2;
    const int seg = tid & 3;
    alignas(16) __nv_bfloat16 hb[32];
    alignas(16) __nv_bfloat16 lb[32];
    #pragma unroll
    for (int v = 0; v < 32; v++) {
        float f = t[j][seg*32 + v];
        __nv_bfloat16 h = __float2bfloat16(f);
        hb[v] = h;
        lb[v] = __float2bfloat16(f - __bfloat162float(h));
    }
    size_t off = (size_t)(c0 + j)*NN + n0 + seg*32;
    uint4* dh = (uint4*)(dhi + off);
    uint4* dl = (uint4*)(dlo + off);
    const uint4* sh = (const uint4*)hb;
    const uint4* sl = (const uint4*)lb;
    #pragma unroll
    for (int q = 0; q < 4; q++) { dh[q] = sh[q]; dl[q] = sl[q]; }
}

// ---------------------------------------------------------------
// K3: pooled weight/bias gen (float4-vectorized)
// ---------------------------------------------------------------
__global__ __launch_bounds__(256) void wgen_kernel(const float* __restrict__ E,
                                                   const float* __restrict__ wpool,
                                                   int KO, int which) {
    int idx4 = (blockIdx.x * 256 + threadIdx.x) * 4;
    if (idx4 >= KO) return;
    float* Wout = which ? g_Wu : g_Wg;
    float4 w[DD];
    #pragma unroll
    for (int d = 0; d < DD; d++) w[d] = *(const float4*)&wpool[d*KO + idx4];
    int n0 = blockIdx.y * 16;
    #pragma unroll 4
    for (int nn = 0; nn < 16; nn++) {
        int n = n0 + nn;
        float4 s = make_float4(0.f, 0.f, 0.f, 0.f);
        #pragma unroll
        for (int d = 0; d < DD; d++) {
            float e = E[n*DD + d];
            s.x += e * w[d].x; s.y += e * w[d].y;
            s.z += e * w[d].z; s.w += e * w[d].w;
        }
        *(float4*)&Wout[(size_t)n*KO + idx4] = s;
    }
}

__global__ __launch_bounds__(256) void bgen_kernel(const float* __restrict__ E,
                                                   const float* __restrict__ bpool,
                                                   int OUT, int which) {
    int idx = blockIdx.x * 256 + threadIdx.x;
    if (idx >= NN*OUT) return;
    float* bout = which ? g_bu : g_bg;
    int n = idx / OUT, o = idx % OUT;
    float s = 0.f;
    #pragma unroll
    for (int d = 0; d < DD; d++) s += E[n*DD + d] * bpool[d*OUT + o];
    bout[idx] = s;
}

// ---------------------------------------------------------------
// K4: HMMA (mma.sync) bf16 split-3 GEMM: C[2048,4224] = S @ X
// CTA 128x128, BK=32, 2-stage cp.async, 8 warps, 2 CTAs/SM.
// ---------------------------------------------------------------
#define BKC      32
#define NCHUNKS  (NN/BKC)          // 64
#define RSTRIDE  80                // bytes per smem row (40 bf16)
#define TILE_B   (128*RSTRIDE)     // 10240 bytes per tile
#define STAGE_B  (4*TILE_B)        // Ahi,Alo,Bhi,Blo = 40960
#define GEMM_SMEM (2*STAGE_B)      // 81920

__global__ __launch_bounds__(256, 2) void hmma_gemm_kernel(int pass) {
    const __nv_bfloat16* __restrict__ Bthi = pass ? g_ct_hi : g_xt_hi;
    const __nv_bfloat16* __restrict__ Btlo = pass ? g_ct_lo : g_xt_lo;
    float* __restrict__ C = pass ? g_cg1 : g_xg1;

    extern __shared__ char smem[];
    const uint32_t sb = smem_to_u32(smem);
    const int tid  = threadIdx.x;
    const int lane = tid & 31;
    const int wid  = tid >> 5;
    const int m0 = blockIdx.y * 128;
    const int n0 = blockIdx.x * 128;
    const int wm = (wid >> 2) * 64;
    const int wn = (wid & 3)  * 32;

    float acc[4][4][4];
    #pragma unroll
    for (int i = 0; i < 4; i++)
        #pragma unroll
        for (int j = 0; j < 4; j++)
            #pragma unroll
            for (int q = 0; q < 4; q++) acc[i][j][q] = 0.f;

    const int lrow = tid >> 2;
    const int lc   = tid & 3;

    {
        #pragma unroll
        for (int h = 0; h < 2; h++) {
            int row = lrow + h*64;
            uint32_t doff = (uint32_t)(row*RSTRIDE + lc*16);
            size_t ga = (size_t)(m0 + row)*NN + lc*8;
            size_t gb = (size_t)(n0 + row)*NN + lc*8;
            cpasync16(sb + 0*TILE_B + doff, g_Shi + ga);
            cpasync16(sb + 1*TILE_B + doff, g_Slo + ga);
            cpasync16(sb + 2*TILE_B + doff, Bthi + gb);
            cpasync16(sb + 3*TILE_B + doff, Btlo + gb);
        }
        CPASYNC_COMMIT();
    }

    for (int kt = 0; kt < NCHUNKS; kt++) {
        if (kt + 1 < NCHUNKS) {
            const uint32_t stg = sb + (uint32_t)(((kt+1) & 1) * STAGE_B);
            const int gk = (kt + 1) * BKC;
            #pragma unroll
            for (int h = 0; h < 2; h++) {
                int row = lrow + h*64;
                uint32_t doff = (uint32_t)(row*RSTRIDE + lc*16);
                size_t ga = (size_t)(m0 + row)*NN + gk + lc*8;
                size_t gb = (size_t)(n0 + row)*NN + gk + lc*8;
                cpasync16(stg + 0*TILE_B + doff, g_Shi + ga);
                cpasync16(stg + 1*TILE_B + doff, g_Slo + ga);
                cpasync16(stg + 2*TILE_B + doff, Bthi + gb);
                cpasync16(stg + 3*TILE_B + doff, Btlo + gb);
            }
            CPASYNC_COMMIT();
            CPASYNC_WAIT(1);
        } else {
            CPASYNC_WAIT(0);
        }
        __syncthreads();

        const uint32_t stg = sb + (uint32_t)((kt & 1) * STAGE_B);
        const int lr16 = lane & 15;
        const int lch  = lane >> 4;
        #pragma unroll
        for (int ks = 0; ks < 2; ks++) {
            const uint32_t aoff = stg + (uint32_t)((wm + lr16)*RSTRIDE + (ks*2 + lch)*16);
            const uint32_t boff = stg + 2*TILE_B + (uint32_t)((wn + lr16)*RSTRIDE + (ks*2 + lch)*16);

            uint32_t ahi[4][4], bhi[2][4];
            #pragma unroll
            for (int mt = 0; mt < 4; mt++)
                LDMX4(ahi[mt], aoff + (uint32_t)(mt*16*RSTRIDE));
            #pragma unroll
            for (int np = 0; np < 2; np++)
                LDMX4(bhi[np], boff + (uint32_t)(np*16*RSTRIDE));
            // pass 1: Ahi*Bhi
            #pragma unroll
            for (int mt = 0; mt < 4; mt++)
                #pragma unroll
                for (int nt = 0; nt < 4; nt++) {
                    int np = nt >> 1, sel = nt & 1;
                    MMA_BF16(acc[mt][nt], ahi[mt], bhi[np][sel], bhi[np][sel+2]);
                }
            // pass 3: Alo*Bhi (load alo late, retire bhi after)
            {
                uint32_t alo[4][4];
                #pragma unroll
                for (int mt = 0; mt < 4; mt++)
                    LDMX4(alo[mt], aoff + TILE_B + (uint32_t)(mt*16*RSTRIDE));
                #pragma unroll
                for (int mt = 0; mt < 4; mt++)
                    #pragma unroll
                    for (int nt = 0; nt < 4; nt++) {
                        int np = nt >> 1, sel = nt & 1;
                        MMA_BF16(acc[mt][nt], alo[mt], bhi[np][sel], bhi[np][sel+2]);
                    }
            }
            // pass 2: Ahi*Blo
            {
                uint32_t blo[2][4];
                #pragma unroll
                for (int np = 0; np < 2; np++)
                    LDMX4(blo[np], boff + TILE_B + (uint32_t)(np*16*RSTRIDE));
                #pragma unroll
                for (int mt = 0; mt < 4; mt++)
                    #pragma unroll
                    for (int nt = 0; nt < 4; nt++) {
                        int np = nt >> 1, sel = nt & 1;
                        MMA_BF16(acc[mt][nt], ahi[mt], blo[np][sel], blo[np][sel+2]);
                    }
            }
        }
        __syncthreads();
    }

    const int erow = lane >> 2;
    const int ecol = (lane & 3) * 2;
    #pragma unroll
    for (int mt = 0; mt < 4; mt++) {
        #pragma unroll
        for (int nt = 0; nt < 4; nt++) {
            int gm = m0 + wm + mt*16 + erow;
            int gc = n0 + wn + nt*8 + ecol;
            float2 v0 = make_float2(acc[mt][nt][0], acc[mt][nt][1]);
            float2 v1 = make_float2(acc[mt][nt][2], acc[mt][nt][3]);
            *(float2*)&C[(size_t)gm*NCOLS + gc]       = v0;
            *(float2*)&C[(size_t)(gm+8)*NCOLS + gc]   = v1;
        }
    }
}

// ---------------------------------------------------------------
// K5: gate per-node HMMA GEMM + sigmoid + candidate build
// A[64][144] = [xin | xg1 | 0pad] hi/lo; W^T[128][144] hi/lo; 8 warps.
// smem rows: 152 bf16 = 304B (19x16B, gcd(19,8)=1 -> conflict-free)
// ---------------------------------------------------------------
#define RS2    152
#define RS2B   304
#define G_AHI  0
#define G_ALO  (64*RS2B)                 // 19456
#define G_WHI  (2*64*RS2B)               // 38912
#define G_WLO  (2*64*RS2B + 128*RS2B)    // 77824
#define GATE_SMEM (2*64*RS2B + 2*128*RS2B)  // 116736

__global__ __launch_bounds__(256) void gate_hmma_kernel(const float* __restrict__ x,
                                                        const float* __restrict__ state) {
    extern __shared__ char smc[];
    const uint32_t sb = smem_to_u32(smc);
    __nv_bfloat16* s16 = (__nv_bfloat16*)smc;
    const int n   = blockIdx.x;
    const int tid = threadIdx.x;
    const int lane = tid & 31, wid = tid >> 5;

    // zero-pad j in [132,144) for A (64 rows) and W (128 rows)
    for (int i = tid; i < (64+128)*12; i += 256) {
        int r = i / 12, j = 132 + (i % 12);
        if (r < 64) {
            s16[(G_AHI>>1) + r*RS2 + j] = __float2bfloat16(0.f);
            s16[(G_ALO>>1) + r*RS2 + j] = __float2bfloat16(0.f);
        } else {
            int o = r - 64;
            s16[(G_WHI>>1) + o*RS2 + j] = __float2bfloat16(0.f);
            s16[(G_WLO>>1) + o*RS2 + j] = __float2bfloat16(0.f);
        }
    }
    // A fill: cols [0,66) from xin, [66,132) from xg1
    {
        const float* xin_n = g_xin + (size_t)n*BB*CIN;
        const float* xg1_n = g_xg1 + (size_t)n*BB*CIN;
        for (int i = tid; i < BB*CIN; i += 256) {
            int b = i / CIN, c = i % CIN;
            float v0 = xin_n[i], v1 = xg1_n[i];
            __nv_bfloat16 h0 = __float2bfloat16(v0);
            __nv_bfloat16 h1 = __float2bfloat16(v1);
            s16[(G_AHI>>1) + b*RS2 + c]      = h0;
            s16[(G_ALO>>1) + b*RS2 + c]      = __float2bfloat16(v0 - __bfloat162float(h0));
            s16[(G_AHI>>1) + b*RS2 + 66 + c] = h1;
            s16[(G_ALO>>1) + b*RS2 + 66 + c] = __float2bfloat16(v1 - __bfloat162float(h1));
        }
    }
    // W fill: gmem [j][o] fp32 -> smem W^T [o][j] hi/lo
    {
        const float* Wn = g_Wg + (size_t)n*KJ*GOUT;
        for (int i = tid; i < KJ*GOUT; i += 256) {
            int j = i >> 7, o = i & 127;
            float w = Wn[i];
            __nv_bfloat16 h = __float2bfloat16(w);
            s16[(G_WHI>>1) + o*RS2 + j] = h;
            s16[(G_WLO>>1) + o*RS2 + j] = __float2bfloat16(w - __bfloat162float(h));
        }
    }
    __syncthreads();

    const int wm = (wid >> 2) * 32;   // 2 m-tiles of 16
    const int wn = (wid & 3) * 32;    // 4 n-tiles of 8
    const int lr16 = lane & 15, lch = lane >> 4;

    float acc[2][4][4];
    #pragma unroll
    for (int i = 0; i < 2; i++)
        #pragma unroll
        for (int j = 0; j < 4; j++)
            #pragma unroll
            for (int q = 0; q < 4; q++) acc[i][j][q] = 0.f;

    #pragma unroll
    for (int k = 0; k < 9; k++) {
        const uint32_t kb = (uint32_t)((k*2 + lch)*16);
        uint32_t ahi[2][4], alo[2][4], bhi[2][4], blo[2][4];
        #pragma unroll
        for (int mt = 0; mt < 2; mt++) {
            uint32_t ao = sb + G_AHI + (uint32_t)((wm + mt*16 + lr16)*RS2B) + kb;
            LDMX4(ahi[mt], ao);
            LDMX4(alo[mt], ao + (G_ALO - G_AHI));
        }
        #pragma unroll
        for (int np = 0; np < 2; np++) {
            uint32_t bo = sb + G_WHI + (uint32_t)((wn + np*16 + lr16)*RS2B) + kb;
            LDMX4(bhi[np], bo);
            LDMX4(blo[np], bo + (G_WLO - G_WHI));
        }
        #pragma unroll
        for (int mt = 0; mt < 2; mt++)
            #pragma unroll
            for (int nt = 0; nt < 4; nt++) {
                int np = nt >> 1, sel = nt & 1;
                MMA_BF16(acc[mt][nt], ahi[mt], bhi[np][sel], bhi[np][sel+2]);
                MMA_BF16(acc[mt][nt], alo[mt], bhi[np][sel], bhi[np][sel+2]);
                MMA_BF16(acc[mt][nt], ahi[mt], blo[np][sel], blo[np][sel+2]);
            }
    }

    // epilogue
    const int er = lane >> 2, ec = (lane & 3) * 2;
    #pragma unroll
    for (int mt = 0; mt < 2; mt++) {
        #pragma unroll
        for (int nt = 0; nt < 4; nt++) {
            int o = wn + nt*8 + ec;
            float bias0 = g_bg[n*GOUT + o];
            float bias1 = g_bg[n*GOUT + o + 1];
            #pragma unroll
            for (int h = 0; h < 2; h++) {
                int b = wm + mt*16 + er + h*8;
                float v0 = 1.f / (1.f + expf(-(acc[mt][nt][h*2+0] + bias0)));
                float v1 = 1.f / (1.f + expf(-(acc[mt][nt][h*2+1] + bias1)));
                if (o < DOUT) {
                    float2 st = *(const float2*)&state[((size_t)b*NN + n)*DOUT + o];
                    *(float2*)&g_cand[((size_t)n*BB + b)*CIN + DIN + o] =
                        make_float2(v0*st.x, v1*st.y);
                } else {
                    *(float2*)&g_r[((size_t)n*BB + b)*DOUT + (o - DOUT)] =
                        make_float2(v0, v1);
                }
            }
        }
    }
    if (tid < 128) {
        int b = tid >> 1, c = tid & 1;
        g_cand[((size_t)n*BB + b)*CIN + c] = x[((size_t)b*NN + n)*DIN + c];
    }
}

// ---------------------------------------------------------------
// K6: update per-node HMMA GEMM + tanh + GRU combine
// ---------------------------------------------------------------
#define U_AHI  0
#define U_ALO  (64*RS2B)
#define U_WHI  (2*64*RS2B)
#define U_WLO  (3*64*RS2B)
#define UPD_SMEM (4*64*RS2B)   // 77824

__global__ __launch_bounds__(256) void update_hmma_kernel(const float* __restrict__ state,
                                                          float* __restrict__ out) {
    extern __shared__ char smc[];
    const uint32_t sb = smem_to_u32(smc);
    __nv_bfloat16* s16 = (__nv_bfloat16*)smc;
    const int n   = blockIdx.x;
    const int tid = threadIdx.x;
    const int lane = tid & 31, wid = tid >> 5;

    for (int i = tid; i < (64+64)*12; i += 256) {
        int r = i / 12, j = 132 + (i % 12);
        if (r < 64) {
            s16[(U_AHI>>1) + r*RS2 + j] = __float2bfloat16(0.f);
            s16[(U_ALO>>1) + r*RS2 + j] = __float2bfloat16(0.f);
        } else {
            int o = r - 64;
            s16[(U_WHI>>1) + o*RS2 + j] = __float2bfloat16(0.f);
            s16[(U_WLO>>1) + o*RS2 + j] = __float2bfloat16(0.f);
        }
    }
    {
        const float* ca_n = g_cand + (size_t)n*BB*CIN;
        const float* cg_n = g_cg1  + (size_t)n*BB*CIN;
        for (int i = tid; i < BB*CIN; i += 256) {
            int b = i / CIN, c = i % CIN;
            float v0 = ca_n[i], v1 = cg_n[i];
            __nv_bfloat16 h0 = __float2bfloat16(v0);
            __nv_bfloat16 h1 = __float2bfloat16(v1);
            s16[(U_AHI>>1) + b*RS2 + c]      = h0;
            s16[(U_ALO>>1) + b*RS2 + c]      = __float2bfloat16(v0 - __bfloat162float(h0));
            s16[(U_AHI>>1) + b*RS2 + 66 + c] = h1;
            s16[(U_ALO>>1) + b*RS2 + 66 + c] = __float2bfloat16(v1 - __bfloat162float(h1));
        }
    }
    {
        const float* Wn = g_Wu + (size_t)n*KJ*UOUT;
        for (int i = tid; i < KJ*UOUT; i += 256) {
            int j = i >> 6, o = i & 63;
            float w = Wn[i];
            __nv_bfloat16 h = __float2bfloat16(w);
            s16[(U_WHI>>1) + o*RS2 + j] = h;
            s16[(U_WLO>>1) + o*RS2 + j] = __float2bfloat16(w - __bfloat162float(h));
        }
    }
    __syncthreads();

    const int wm = (wid >> 2) * 32;   // 2 m-tiles
    const int wn = (wid & 3) * 16;    // 2 n-tiles of 8
    const int lr16 = lane & 15, lch = lane >> 4;

    float acc[2][2][4];
    #pragma unroll
    for (int i = 0; i < 2; i++)
        #pragma unroll
        for (int j = 0; j < 2; j++)
            #pragma unroll
            for (int q = 0; q < 4; q++) acc[i][j][q] = 0.f;

    #pragma unroll
    for (int k = 0; k < 9; k++) {
        const uint32_t kb = (uint32_t)((k*2 + lch)*16);
        uint32_t ahi[2][4], alo[2][4], bhi[4], blo[4];
        #pragma unroll
        for (int mt = 0; mt < 2; mt++) {
            uint32_t ao = sb + U_AHI + (uint32_t)((wm + mt*16 + lr16)*RS2B) + kb;
            LDMX4(ahi[mt], ao);
            LDMX4(alo[mt], ao + (U_ALO - U_AHI));
        }
        {
            uint32_t bo = sb + U_WHI + (uint32_t)((wn + lr16)*RS2B) + kb;
            LDMX4(bhi, bo);
            LDMX4(blo, bo + (U_WLO - U_WHI));
        }
        #pragma unroll
        for (int mt = 0; mt < 2; mt++)
            #pragma unroll
            for (int nt = 0; nt < 2; nt++) {
                MMA_BF16(acc[mt][nt], ahi[mt], bhi[nt], bhi[nt+2]);
                MMA_BF16(acc[mt][nt], alo[mt], bhi[nt], bhi[nt+2]);
                MMA_BF16(acc[mt][nt], ahi[mt], blo[nt], blo[nt+2]);
            }
    }

    const int er = lane >> 2, ec = (lane & 3) * 2;
    #pragma unroll
    for (int mt = 0; mt < 2; mt++) {
        #pragma unroll
        for (int nt = 0; nt < 2; nt++) {
            int o = wn + nt*8 + ec;
            float bias0 = g_bu[n*UOUT + o];
            float bias1 = g_bu[n*UOUT + o + 1];
            #pragma unroll
            for (int h = 0; h < 2; h++) {
                int b = wm + mt*16 + er + h*8;
                float hc0 = tanhf(acc[mt][nt][h*2+0] + bias0);
                float hc1 = tanhf(acc[mt][nt][h*2+1] + bias1);
                float2 r  = *(const float2*)&g_r[((size_t)n*BB + b)*DOUT + o];
                float2 st = *(const float2*)&state[((size_t)b*NN + n)*DOUT + o];
                *(float2*)&out[((size_t)b*NN + n)*DOUT + o] =
                    make_float2(r.x*st.x + (1.f - r.x)*hc0,
                                r.y*st.y + (1.f - r.y)*hc1);
            }
        }
    }
}

// ---------------------------------------------------------------
extern "C" void kernel_launch(void* const* d_in, const int* in_sizes, int n_in,
                              void* d_out, int out_size) {
    const float* x     = (const float*)d_in[0];  // [B,N,2]
    const float* state = (const float*)d_in[1];  // [B,N,64]
    const float* E     = (const float*)d_in[2];  // [N,10]
    const float* gw    = (const float*)d_in[3];  // [10,2,66,128]
    const float* gb    = (const float*)d_in[4];  // [10,128]
    const float* uw    = (const float*)d_in[5];  // [10,2,66,64]
    const float* ub    = (const float*)d_in[6];  // [10,64]
    float* out = (float*)d_out;

    cudaFuncSetAttribute(hmma_gemm_kernel,   cudaFuncAttributeMaxDynamicSharedMemorySize, GEMM_SMEM);
    cudaFuncSetAttribute(gate_hmma_kernel,   cudaFuncAttributeMaxDynamicSharedMemorySize, GATE_SMEM);
    cudaFuncSetAttribute(update_hmma_kernel, cudaFuncAttributeMaxDynamicSharedMemorySize, UPD_SMEM);

    // 1. adjacency supports -> bf16 hi/lo
    supports_kernel<<<NN, 256>>>(E);
    // 2. concat(x, state) fp32 node-major
    concat_kernel<<<(NN*BB*CIN + 255)/256, 256>>>(x, state);
    // 3. transpose + bf16 split of xin
    transconv_kernel<<<dim3(NCOLS/64, NN/128), 256>>>(0);
    // 4-5. pooled weights
    wgen_kernel<<<dim3((KJ*GOUT/4 + 255)/256, NN/16), 256>>>(E, gw, KJ*GOUT, 0);
    wgen_kernel<<<dim3((KJ*UOUT/4 + 255)/256, NN/16), 256>>>(E, uw, KJ*UOUT, 1);
    // 6. xg1 = S @ xin  (HMMA) — 6th launch for ncu -s 5 -c 1 capture
    hmma_gemm_kernel<<<dim3(NCOLS/128, NN/128), 256, GEMM_SMEM>>>(0);
    // 7-8. pooled biases
    bgen_kernel<<<(NN*GOUT + 255)/256, 256>>>(E, gb, GOUT, 0);
    bgen_kernel<<<(NN*UOUT + 255)/256, 256>>>(E, ub, UOUT, 1);
    // 9. gate: z,r + candidate (HMMA)
    gate_hmma_kernel<<<NN, 256, GATE_SMEM>>>(x, state);
    // 10. transpose + bf16 split of cand
    transconv_kernel<<<dim3(NCOLS/64, NN/128), 256>>>(1);
    // 11. cg1 = S @ cand (HMMA)
    hmma_gemm_kernel<<<dim3(NCOLS/128, NN/128), 256, GEMM_SMEM>>>(1);
    // 12. update: hc + GRU combine -> out (HMMA)
    update_hmma_kernel<<<NN, 256, UPD_SMEM>>>(state, out);
}